// round 3
// baseline (speedup 1.0000x reference)
#include <cuda_runtime.h>

// TropicalDense: out[b,o] = max_{s in {0,1}, d} ( (s?-X[b,d]:X[b,d]) + K[s,d,o] )
// B=1024, D=512, O=256, float32.

#define B_DIM 1024
#define D_DIM 512
#define O_DIM 256

#define BM 32    // batch rows per block
#define BO 32    // output cols per block
#define DC 64    // d-chunk through shared
#define NTHREADS 256
#define XP_STRIDE 34   // BM+2 float2: keeps 16B alignment (34*8=272=16*17), kills store conflicts

// packed f32x2 add: (a.lo+b.lo, a.hi+b.hi) in one fma-pipe instruction
__device__ __forceinline__ void addx2(unsigned long long a, unsigned long long b,
                                      float& lo, float& hi) {
    unsigned long long d;
    asm("add.rn.f32x2 %0, %1, %2;" : "=l"(d) : "l"(a), "l"(b));
    asm("mov.b64 {%0, %1}, %2;" : "=f"(lo), "=f"(hi) : "l"(d));
}

__global__ void __launch_bounds__(NTHREADS, 2)
tropical_dense_kernel(const float* __restrict__ X,
                      const float* __restrict__ K,
                      float* __restrict__ out) {
    // Xp[dd][row] = (x, -x)   pre-negated pairs
    __shared__ float2 Xp[DC][XP_STRIDE];
    // Kp[dd][col] = (K0[d][o], K1[d][o])
    __shared__ float2 Kp[DC][BO];

    const int tid = threadIdx.x;
    const int to  = tid & 15;     // 0..15 output lane
    const int tb  = tid >> 4;     // 0..15 batch group (2 rows each)
    const int b0  = blockIdx.y * BM;
    const int o0  = blockIdx.x * BO;

    float acc[2][2];
    #pragma unroll
    for (int i = 0; i < 2; i++)
        #pragma unroll
        for (int j = 0; j < 2; j++)
            acc[i][j] = __int_as_float(0xff800000);   // -inf

    for (int dc = 0; dc < D_DIM; dc += DC) {
        // ---- X tile: 32 rows x 64 d, float4-coalesced, store transposed pre-negated ----
        #pragma unroll
        for (int k = 0; k < (BM * DC / 4) / NTHREADS; k++) {   // 2 iters
            int t    = tid + k * NTHREADS;   // 0..511 float4 slots
            int col4 = t & 15;               // float4 index along d
            int row  = t >> 4;               // 0..31
            float4 v = *reinterpret_cast<const float4*>(
                &X[(size_t)(b0 + row) * D_DIM + dc + col4 * 4]);
            Xp[col4 * 4 + 0][row] = make_float2(v.x, -v.x);
            Xp[col4 * 4 + 1][row] = make_float2(v.y, -v.y);
            Xp[col4 * 4 + 2][row] = make_float2(v.z, -v.z);
            Xp[col4 * 4 + 3][row] = make_float2(v.w, -v.w);
        }
        // ---- K tile: interleave (K0,K1), float4-coalesced ----
        #pragma unroll
        for (int k = 0; k < (DC * BO / 4) / NTHREADS; k++) {   // 2 iters
            int t   = tid + k * NTHREADS;    // 0..511 float4 slots
            int oo4 = t & 7;                 // float4 index along o (8 per row)
            int dd  = t >> 3;                // 0..63
            const float* p0 = &K[(size_t)(dc + dd) * O_DIM + o0 + oo4 * 4];
            float4 a = *reinterpret_cast<const float4*>(p0);
            float4 b = *reinterpret_cast<const float4*>(p0 + (size_t)D_DIM * O_DIM);
            Kp[dd][oo4 * 4 + 0] = make_float2(a.x, b.x);
            Kp[dd][oo4 * 4 + 1] = make_float2(a.y, b.y);
            Kp[dd][oo4 * 4 + 2] = make_float2(a.z, b.z);
            Kp[dd][oo4 * 4 + 3] = make_float2(a.w, b.w);
        }
        __syncthreads();

        // ---- hot loop: per dd = 3 LDS + 4 ADDX2(fma) + 8 FMNMX(alu) -> alu-bound ----
        #pragma unroll 8
        for (int dd = 0; dd < DC; dd++) {
            const unsigned long long* xr =
                reinterpret_cast<const unsigned long long*>(&Xp[dd][tb * 2]);
            unsigned long long xp0 = xr[0];          // (x0, -x0)
            unsigned long long xp1 = xr[1];          // (x1, -x1)
            unsigned long long kp0 =
                *reinterpret_cast<const unsigned long long*>(&Kp[dd][to]);
            unsigned long long kp1 =
                *reinterpret_cast<const unsigned long long*>(&Kp[dd][to + 16]);
            float lo, hi;
            addx2(xp0, kp0, lo, hi);  acc[0][0] = fmaxf(acc[0][0], fmaxf(lo, hi));
            addx2(xp0, kp1, lo, hi);  acc[0][1] = fmaxf(acc[0][1], fmaxf(lo, hi));
            addx2(xp1, kp0, lo, hi);  acc[1][0] = fmaxf(acc[1][0], fmaxf(lo, hi));
            addx2(xp1, kp1, lo, hi);  acc[1][1] = fmaxf(acc[1][1], fmaxf(lo, hi));
        }
        __syncthreads();
    }

    #pragma unroll
    for (int i = 0; i < 2; i++)
        #pragma unroll
        for (int j = 0; j < 2; j++)
            out[(size_t)(b0 + tb * 2 + i) * O_DIM + o0 + to + 16 * j] = acc[i][j];
}

extern "C" void kernel_launch(void* const* d_in, const int* in_sizes, int n_in,
                              void* d_out, int out_size) {
    const float* X = (const float*)d_in[0];   // [1024, 512]
    const float* K = (const float*)d_in[1];   // [2, 512, 256]
    float* out     = (float*)d_out;           // [1024, 256]

    dim3 grid(O_DIM / BO, B_DIM / BM);        // (8, 32) = 256 blocks
    tropical_dense_kernel<<<grid, NTHREADS>>>(X, K, out);
}